// round 1
// baseline (speedup 1.0000x reference)
#include <cuda_runtime.h>
#include <math.h>

#define NIMG 256
#define EMB  1600
#define HIDD 400
#define KNBR 11   // self + 10 neighbors

// ---------------- scratch (__device__ globals; no allocs allowed) ----------------
__device__ float g_conv[(size_t)NIMG*64*84*84];   // conv output tmp (reused per block)
__device__ float g_bufA[(size_t)NIMG*64*42*42];   // pooled ping
__device__ float g_bufB[(size_t)NIMG*64*21*21];   // pooled pong (final z lives here)
__device__ float g_wt[64*9*64];                   // transposed weights [ic][tap][oc]
__device__ float g_part[2*64*NIMG];               // per-(c,n) partial sums / sumsq
__device__ float g_sum[64];
__device__ float g_sumsq[64];
__device__ float g_zn[NIMG*EMB];
__device__ float g_znT[EMB*NIMG];
__device__ float g_sim[NIMG*NIMG];
__device__ int   g_nbr[NIMG*KNBR];
__device__ float g_xl1[NIMG*HIDD];
__device__ float g_xr1[NIMG*HIDD];
__device__ float g_h1 [NIMG*HIDD];
__device__ float g_xl2[(size_t)NIMG*4*EMB];
__device__ float g_xr2[(size_t)NIMG*4*EMB];

// ---------------- weight transpose: OIHW -> [ic][tap][oc] ----------------
__global__ void prep_kernel(const float* __restrict__ w, int CIN) {
    int i = blockIdx.x*256 + threadIdx.x;
    int total = 64*CIN*9;
    if (i < total) {
        int oc = i / (CIN*9);
        int rest = i % (CIN*9);
        int ic = rest / 9;
        int t  = rest % 9;
        g_wt[ic*576 + t*64 + oc] = w[i];
    }
}

// ---------------- 3x3 SAME conv + bias ----------------
// Tile 16x8 output pixels per CTA (128 threads), each thread accumulates all 64 oc.
#define CTW 16
#define CTH 8
template<int CIN>
__global__ __launch_bounds__(128) void conv3x3_kernel(
        const float* __restrict__ in, const float* __restrict__ bias,
        float* __restrict__ out, int H, int W, int tilesX) {
    int n    = blockIdx.y;
    int tile = blockIdx.x;
    int ty0  = (tile / tilesX) * CTH;
    int tx0  = (tile % tilesX) * CTW;
    int tid  = threadIdx.x;
    int r = tid / CTW, c = tid % CTW;
    int oy = ty0 + r, ox = tx0 + c;

    __shared__ float s_in[(CTH+2)*(CTW+2)];
    __shared__ __align__(16) float s_w[9*64];

    float acc[64];
#pragma unroll
    for (int i = 0; i < 64; i++) acc[i] = 0.f;

    const float* inN = in + (size_t)n * CIN * H * W;
    for (int ic = 0; ic < CIN; ic++) {
        for (int i = tid; i < (CTH+2)*(CTW+2); i += 128) {
            int ly = i / (CTW+2), lx = i % (CTW+2);
            int gy = ty0 + ly - 1, gx = tx0 + lx - 1;
            float v = 0.f;
            if (gy >= 0 && gy < H && gx >= 0 && gx < W)
                v = inN[(size_t)ic*H*W + gy*W + gx];
            s_in[i] = v;
        }
        for (int i = tid; i < 576; i += 128) s_w[i] = g_wt[ic*576 + i];
        __syncthreads();
#pragma unroll
        for (int ky = 0; ky < 3; ky++)
#pragma unroll
        for (int kx = 0; kx < 3; kx++) {
            float v = s_in[(r+ky)*(CTW+2) + (c+kx)];
            const float4* w4 = (const float4*)&s_w[(ky*3+kx)*64];
#pragma unroll
            for (int o = 0; o < 16; o++) {
                float4 w = w4[o];
                acc[4*o+0] += v*w.x; acc[4*o+1] += v*w.y;
                acc[4*o+2] += v*w.z; acc[4*o+3] += v*w.w;
            }
        }
        __syncthreads();
    }
    if (oy < H && ox < W) {
        size_t base = (size_t)n*64*H*W + (size_t)oy*W + ox;
#pragma unroll
        for (int oc = 0; oc < 64; oc++)
            out[base + (size_t)oc*H*W] = acc[oc] + bias[oc];
    }
}

// ---------------- BN statistics (deterministic two-stage) ----------------
__global__ void stats_kernel(const float* __restrict__ x, int HW) {
    int c = blockIdx.x, n = blockIdx.y;
    const float* p = x + ((size_t)n*64 + c) * HW;
    float s = 0.f, ss = 0.f;
    for (int i = threadIdx.x; i < HW; i += 256) { float v = p[i]; s += v; ss += v*v; }
    __shared__ float rs[256], rss[256];
    rs[threadIdx.x] = s; rss[threadIdx.x] = ss;
    __syncthreads();
    for (int o = 128; o > 0; o >>= 1) {
        if (threadIdx.x < o) { rs[threadIdx.x] += rs[threadIdx.x+o]; rss[threadIdx.x] += rss[threadIdx.x+o]; }
        __syncthreads();
    }
    if (threadIdx.x == 0) {
        g_part[c*NIMG + n]           = rs[0];
        g_part[64*NIMG + c*NIMG + n] = rss[0];
    }
}

__global__ void stats_final_kernel() {
    int c = threadIdx.x;  // 64 threads
    float s = 0.f, ss = 0.f;
    for (int n = 0; n < NIMG; n++) { s += g_part[c*NIMG+n]; ss += g_part[64*NIMG + c*NIMG + n]; }
    g_sum[c] = s; g_sumsq[c] = ss;
}

// ---------------- BN + ReLU + 2x2 maxpool ----------------
__global__ void bnpool_kernel(const float* __restrict__ x,
                              const float* __restrict__ g, const float* __restrict__ b,
                              float* __restrict__ out,
                              int H, int W, int Ho, int Wo, float invCnt, int total) {
    int idx = blockIdx.x*256 + threadIdx.x;
    if (idx >= total) return;
    int wo = idx % Wo;
    int ho = (idx / Wo) % Ho;
    int c  = (idx / (Wo*Ho)) % 64;
    int n  =  idx / (Wo*Ho*64);
    float mean = g_sum[c] * invCnt;
    float var  = g_sumsq[c] * invCnt - mean*mean;
    float rinv = rsqrtf(var + 1e-5f);
    float scale = rinv * g[c];
    float shift = b[c] - mean * scale;
    size_t base = ((size_t)n*64 + c) * H * W + (size_t)(2*ho)*W + 2*wo;
    float a0 = fmaf(x[base],       scale, shift);
    float a1 = fmaf(x[base+1],     scale, shift);
    float a2 = fmaf(x[base+W],     scale, shift);
    float a3 = fmaf(x[base+W+1],   scale, shift);
    float m = fmaxf(fmaxf(a0,a1), fmaxf(a2,a3));
    out[idx] = m > 0.f ? m : 0.f;
}

// ---------------- cosine normalize z -> zn, znT ----------------
__global__ void znorm_kernel(const float* __restrict__ z) {
    int n = blockIdx.x;
    __shared__ float red[256];
    float s = 0.f;
    for (int k = threadIdx.x; k < EMB; k += 256) { float v = z[(size_t)n*EMB+k]; s += v*v; }
    red[threadIdx.x] = s; __syncthreads();
    for (int o = 128; o > 0; o >>= 1) {
        if (threadIdx.x < o) red[threadIdx.x] += red[threadIdx.x+o];
        __syncthreads();
    }
    float rinv = rsqrtf(red[0] + 1e-12f);
    for (int k = threadIdx.x; k < EMB; k += 256) {
        float v = z[(size_t)n*EMB+k] * rinv;
        g_zn[(size_t)n*EMB+k] = v;
        g_znT[(size_t)k*NIMG+n] = v;
    }
}

// ---------------- sim = zn @ zn^T with -inf diagonal ----------------
__global__ void sim_kernel() {
    int n = blockIdx.x;
    int m = threadIdx.x;  // 256
    __shared__ float s_z[EMB];
    for (int k = m; k < EMB; k += 256) s_z[k] = g_zn[(size_t)n*EMB+k];
    __syncthreads();
    float acc = 0.f;
    for (int k = 0; k < EMB; k++) acc += s_z[k] * g_znT[(size_t)k*NIMG + m];
    g_sim[n*NIMG + m] = (m == n) ? -1e30f : acc;
}

// ---------------- per-row top-10 ----------------
__global__ void topk_kernel() {
    int n = blockIdx.x*blockDim.x + threadIdx.x;
    if (n >= NIMG) return;
    float bv[10]; int bi[10];
#pragma unroll
    for (int i = 0; i < 10; i++) { bv[i] = -1e38f; bi[i] = -1; }
    for (int m = 0; m < NIMG; m++) {
        float v = g_sim[n*NIMG + m];
        if (v > bv[9]) {
            int p = 9;
            while (p > 0 && bv[p-1] < v) { bv[p] = bv[p-1]; bi[p] = bi[p-1]; p--; }
            bv[p] = v; bi[p] = m;
        }
    }
    g_nbr[n*KNBR] = n;
    for (int i = 0; i < 10; i++) g_nbr[n*KNBR + 1 + i] = bi[i];
}

// ---------------- tiled SGEMM: C[M,N] = A[M,K] @ B[K,N] (K % 16 == 0) ----------------
__global__ __launch_bounds__(256) void sgemm_kernel(
        const float* __restrict__ A, const float* __restrict__ B, float* __restrict__ C,
        int M, int N, int K) {
    __shared__ float As[16][64];
    __shared__ float Bs[16][64];
    int tid = threadIdx.x;
    int tx = tid & 15, ty = tid >> 4;
    int bm = blockIdx.y*64, bn = blockIdx.x*64;
    float acc[16];
#pragma unroll
    for (int i = 0; i < 16; i++) acc[i] = 0.f;

    int am  = tid >> 2;
    int ak  = (tid & 3) * 4;
    int bk  = tid >> 4;
    int bn4 = (tid & 15) * 4;

    for (int k0 = 0; k0 < K; k0 += 16) {
        float4 a = make_float4(0.f,0.f,0.f,0.f);
        if (bm + am < M) a = *(const float4*)&A[(size_t)(bm+am)*K + k0 + ak];
        As[ak+0][am] = a.x; As[ak+1][am] = a.y; As[ak+2][am] = a.z; As[ak+3][am] = a.w;
        float4 b;
        if (bn + bn4 + 3 < N) {
            b = *(const float4*)&B[(size_t)(k0+bk)*N + bn + bn4];
        } else {
            const float* bp = &B[(size_t)(k0+bk)*N];
            b.x = (bn+bn4+0 < N) ? bp[bn+bn4+0] : 0.f;
            b.y = (bn+bn4+1 < N) ? bp[bn+bn4+1] : 0.f;
            b.z = (bn+bn4+2 < N) ? bp[bn+bn4+2] : 0.f;
            b.w = (bn+bn4+3 < N) ? bp[bn+bn4+3] : 0.f;
        }
        Bs[bk][bn4+0] = b.x; Bs[bk][bn4+1] = b.y; Bs[bk][bn4+2] = b.z; Bs[bk][bn4+3] = b.w;
        __syncthreads();
#pragma unroll
        for (int k = 0; k < 16; k++) {
            float4 av = *(const float4*)&As[k][ty*4];
            float4 bv = *(const float4*)&Bs[k][tx*4];
            acc[ 0] += av.x*bv.x; acc[ 1] += av.x*bv.y; acc[ 2] += av.x*bv.z; acc[ 3] += av.x*bv.w;
            acc[ 4] += av.y*bv.x; acc[ 5] += av.y*bv.y; acc[ 6] += av.y*bv.z; acc[ 7] += av.y*bv.w;
            acc[ 8] += av.z*bv.x; acc[ 9] += av.z*bv.y; acc[10] += av.z*bv.z; acc[11] += av.z*bv.w;
            acc[12] += av.w*bv.x; acc[13] += av.w*bv.y; acc[14] += av.w*bv.z; acc[15] += av.w*bv.w;
        }
        __syncthreads();
    }
#pragma unroll
    for (int i = 0; i < 4; i++) {
        int row = bm + ty*4 + i;
        if (row < M) {
#pragma unroll
            for (int j = 0; j < 4; j++) {
                int col = bn + tx*4 + j;
                if (col < N) C[(size_t)row*N + col] = acc[i*4+j];
            }
        }
    }
}

// ---------------- GATv2 layer 1: EMB->4x100 concat, ReLU(out+bias) ----------------
__global__ __launch_bounds__(128) void gat1_kernel(
        const float* __restrict__ att, const float* __restrict__ bias) {
    int n = blockIdx.x, tid = threadIdx.x;
    __shared__ float s_xr[HIDD];
    __shared__ float s_log[44], s_alpha[44];
    __shared__ int s_nbr[KNBR];
    if (tid < KNBR) s_nbr[tid] = g_nbr[n*KNBR + tid];
    for (int i = tid; i < HIDD; i += 128) s_xr[i] = g_xr1[(size_t)n*HIDD + i];
    __syncthreads();
    int h = tid >> 5, lane = tid & 31;
    for (int k = 0; k < KNBR; k++) {
        const float* xj = &g_xl1[(size_t)s_nbr[k]*HIDD + h*100];
        const float* xr = &s_xr[h*100];
        const float* at = &att[h*100];
        float p = 0.f;
        for (int c = lane; c < 100; c += 32) {
            float e = xr[c] + xj[c];
            e = e > 0.f ? e : 0.2f*e;
            p += e * at[c];
        }
        p += __shfl_down_sync(0xffffffffu, p, 16);
        p += __shfl_down_sync(0xffffffffu, p, 8);
        p += __shfl_down_sync(0xffffffffu, p, 4);
        p += __shfl_down_sync(0xffffffffu, p, 2);
        p += __shfl_down_sync(0xffffffffu, p, 1);
        if (lane == 0) s_log[k*4 + h] = p;
    }
    __syncthreads();
    if (tid < 4) {
        float mx = -1e30f;
        for (int k = 0; k < KNBR; k++) mx = fmaxf(mx, s_log[k*4+tid]);
        float sm = 0.f;
        for (int k = 0; k < KNBR; k++) { float e = expf(s_log[k*4+tid] - mx); s_alpha[k*4+tid] = e; sm += e; }
        float inv = 1.f / sm;
        for (int k = 0; k < KNBR; k++) s_alpha[k*4+tid] *= inv;
    }
    __syncthreads();
    for (int c = tid; c < HIDD; c += 128) {
        int hh = c / 100;
        float s = 0.f;
        for (int k = 0; k < KNBR; k++) s += s_alpha[k*4+hh] * g_xl1[(size_t)s_nbr[k]*HIDD + c];
        s += bias[c];
        g_h1[(size_t)n*HIDD + c] = s > 0.f ? s : 0.f;
    }
}

// ---------------- GATv2 layer 2: HID->4x1600, head-averaged, +bias ----------------
__global__ __launch_bounds__(256) void gat2_kernel(
        const float* __restrict__ att, const float* __restrict__ bias,
        float* __restrict__ outzg) {
    int n = blockIdx.x, tid = threadIdx.x;
    __shared__ float s_xr[4*EMB];
    __shared__ float s_log[44], s_alpha[44];
    __shared__ float s_red[8];
    __shared__ int s_nbr[KNBR];
    if (tid < KNBR) s_nbr[tid] = g_nbr[n*KNBR + tid];
    for (int i = tid; i < 4*EMB; i += 256) s_xr[i] = g_xr2[(size_t)n*4*EMB + i];
    __syncthreads();
    int h = tid >> 6, lane = tid & 63;
    for (int k = 0; k < KNBR; k++) {
        const float* xj = &g_xl2[(size_t)s_nbr[k]*4*EMB + (size_t)h*EMB];
        const float* xr = &s_xr[h*EMB];
        const float* at = &att[h*EMB];
        float p = 0.f;
        for (int c = lane; c < EMB; c += 64) {
            float e = xr[c] + xj[c];
            e = e > 0.f ? e : 0.2f*e;
            p += e * at[c];
        }
        p += __shfl_down_sync(0xffffffffu, p, 16);
        p += __shfl_down_sync(0xffffffffu, p, 8);
        p += __shfl_down_sync(0xffffffffu, p, 4);
        p += __shfl_down_sync(0xffffffffu, p, 2);
        p += __shfl_down_sync(0xffffffffu, p, 1);
        if ((tid & 31) == 0) s_red[tid >> 5] = p;
        __syncthreads();
        if (tid < 4) s_log[k*4 + tid] = s_red[2*tid] + s_red[2*tid+1];
        __syncthreads();
    }
    if (tid < 4) {
        float mx = -1e30f;
        for (int k = 0; k < KNBR; k++) mx = fmaxf(mx, s_log[k*4+tid]);
        float sm = 0.f;
        for (int k = 0; k < KNBR; k++) { float e = expf(s_log[k*4+tid] - mx); s_alpha[k*4+tid] = e; sm += e; }
        float inv = 1.f / sm;
        for (int k = 0; k < KNBR; k++) s_alpha[k*4+tid] *= inv;
    }
    __syncthreads();
    for (int c = tid; c < EMB; c += 256) {
        float s = 0.f;
#pragma unroll
        for (int hh = 0; hh < 4; hh++) {
            float ph = 0.f;
            for (int k = 0; k < KNBR; k++)
                ph += s_alpha[k*4+hh] * g_xl2[(size_t)s_nbr[k]*4*EMB + (size_t)hh*EMB + c];
            s += ph;
        }
        outzg[(size_t)n*EMB + c] = 0.25f*s + bias[c];
    }
}

// ---------------- launch ----------------
extern "C" void kernel_launch(void* const* d_in, const int* in_sizes, int n_in,
                              void* d_out, int out_size) {
    const float* x = (const float*)d_in[0];
    const float* cw[4] = {(const float*)d_in[1], (const float*)d_in[5], (const float*)d_in[9],  (const float*)d_in[13]};
    const float* cb[4] = {(const float*)d_in[2], (const float*)d_in[6], (const float*)d_in[10], (const float*)d_in[14]};
    const float* bg[4] = {(const float*)d_in[3], (const float*)d_in[7], (const float*)d_in[11], (const float*)d_in[15]};
    const float* bb[4] = {(const float*)d_in[4], (const float*)d_in[8], (const float*)d_in[12], (const float*)d_in[16]};
    const float* wl1 = (const float*)d_in[17];
    const float* wr1 = (const float*)d_in[18];
    const float* att1 = (const float*)d_in[19];
    const float* bias1 = (const float*)d_in[20];
    const float* wl2 = (const float*)d_in[21];
    const float* wr2 = (const float*)d_in[22];
    const float* att2 = (const float*)d_in[23];
    const float* bias2 = (const float*)d_in[24];
    float* out = (float*)d_out;

    float *conv, *bufA, *bufB, *xl1p, *xr1p, *h1p, *xl2p, *xr2p;
    cudaGetSymbolAddress((void**)&conv, g_conv);
    cudaGetSymbolAddress((void**)&bufA, g_bufA);
    cudaGetSymbolAddress((void**)&bufB, g_bufB);
    cudaGetSymbolAddress((void**)&xl1p, g_xl1);
    cudaGetSymbolAddress((void**)&xr1p, g_xr1);
    cudaGetSymbolAddress((void**)&h1p,  g_h1);
    cudaGetSymbolAddress((void**)&xl2p, g_xl2);
    cudaGetSymbolAddress((void**)&xr2p, g_xr2);

    // ---- block 1: 84x84, CIN=3 ----
    prep_kernel<<<(64*3*9 + 255)/256, 256>>>(cw[0], 3);
    conv3x3_kernel<3><<<dim3(6*11, NIMG), 128>>>(x, cb[0], conv, 84, 84, 6);
    stats_kernel<<<dim3(64, NIMG), 256>>>(conv, 84*84);
    stats_final_kernel<<<1, 64>>>();
    {
        int total = NIMG*64*42*42;
        bnpool_kernel<<<(total+255)/256, 256>>>(conv, bg[0], bb[0], bufA, 84, 84, 42, 42, 1.f/(256.f*84.f*84.f), total);
    }
    // ---- block 2: 42x42, CIN=64 ----
    prep_kernel<<<(64*64*9 + 255)/256, 256>>>(cw[1], 64);
    conv3x3_kernel<64><<<dim3(3*6, NIMG), 128>>>(bufA, cb[1], conv, 42, 42, 3);
    stats_kernel<<<dim3(64, NIMG), 256>>>(conv, 42*42);
    stats_final_kernel<<<1, 64>>>();
    {
        int total = NIMG*64*21*21;
        bnpool_kernel<<<(total+255)/256, 256>>>(conv, bg[1], bb[1], bufB, 42, 42, 21, 21, 1.f/(256.f*42.f*42.f), total);
    }
    // ---- block 3: 21x21 ----
    prep_kernel<<<(64*64*9 + 255)/256, 256>>>(cw[2], 64);
    conv3x3_kernel<64><<<dim3(2*3, NIMG), 128>>>(bufB, cb[2], conv, 21, 21, 2);
    stats_kernel<<<dim3(64, NIMG), 256>>>(conv, 21*21);
    stats_final_kernel<<<1, 64>>>();
    {
        int total = NIMG*64*10*10;
        bnpool_kernel<<<(total+255)/256, 256>>>(conv, bg[2], bb[2], bufA, 21, 21, 10, 10, 1.f/(256.f*441.f), total);
    }
    // ---- block 4: 10x10 ----
    prep_kernel<<<(64*64*9 + 255)/256, 256>>>(cw[3], 64);
    conv3x3_kernel<64><<<dim3(1*2, NIMG), 128>>>(bufA, cb[3], conv, 10, 10, 1);
    stats_kernel<<<dim3(64, NIMG), 256>>>(conv, 10*10);
    stats_final_kernel<<<1, 64>>>();
    {
        int total = NIMG*64*5*5;
        bnpool_kernel<<<(total+255)/256, 256>>>(conv, bg[3], bb[3], bufB, 10, 10, 5, 5, 1.f/(256.f*100.f), total);
    }

    // z = bufB viewed as [256, 1600]; z_cnn -> first half of output
    cudaMemcpyAsync(out, bufB, (size_t)NIMG*EMB*sizeof(float), cudaMemcpyDeviceToDevice);

    // ---- graph construction ----
    znorm_kernel<<<NIMG, 256>>>(bufB);
    sim_kernel<<<NIMG, 256>>>();
    topk_kernel<<<1, 256>>>();

    // ---- GATv2 layer 1 ----
    sgemm_kernel<<<dim3((HIDD+63)/64, (NIMG+63)/64), 256>>>(bufB, wl1, xl1p, NIMG, HIDD, EMB);
    sgemm_kernel<<<dim3((HIDD+63)/64, (NIMG+63)/64), 256>>>(bufB, wr1, xr1p, NIMG, HIDD, EMB);
    gat1_kernel<<<NIMG, 128>>>(att1, bias1);

    // ---- GATv2 layer 2 ----
    sgemm_kernel<<<dim3((4*EMB+63)/64, (NIMG+63)/64), 256>>>(h1p, wl2, xl2p, NIMG, 4*EMB, HIDD);
    sgemm_kernel<<<dim3((4*EMB+63)/64, (NIMG+63)/64), 256>>>(h1p, wr2, xr2p, NIMG, 4*EMB, HIDD);
    gat2_kernel<<<NIMG, 256>>>(att2, bias2, out + (size_t)NIMG*EMB);
}